// round 12
// baseline (speedup 1.0000x reference)
#include <cuda_runtime.h>

#define E    4096
#define NVAR 1024
#define NCHK 512
#define NBLK 256
#define EPS32   1.1920929e-07f
#define LN2F    0.6931471805599453f

// Upper-triangle peers of each edge (columns > row), ascending. Rows with
// cntA+cntB==7 (check representatives) have complete sorted lists; only those
// are ever read by decode.
__device__ int g_up[E * 7];
__device__ __align__(16) int g_cntA[E];   // peers found in cols [0,2048)
__device__ __align__(16) int g_cntB[E];   // peers found in cols [2048,4096)
__device__ unsigned g_done = 0;           // grid handshake (reset every run)

// ---------------- math helpers -----------------------------------------------
__device__ __forceinline__ float tanh_acc(float a) {
    // tanh(a) = 1 - 2/(exp(2a)+1); inf-safe (saturates to +-1 exactly)
    return 1.0f - __fdividef(2.0f, __expf(2.0f * a) + 1.0f);
}

__device__ __forceinline__ float atanh2(float v) {
    // reference clamps: v>=1 -> 1-eps, v<=-1 -> -1+eps (exact copy)
    v = (v >= 1.0f) ? (1.0f - EPS32) : v;
    v = (v <= -1.0f) ? (-1.0f + EPS32) : v;
    // 2*atanh(v) = ln2*(lg2(1+v) - lg2(1-v)); two independent MUFU lg2
    return LN2F * (__log2f(1.0f + v) - __log2f(1.0f - v));
}

__device__ __forceinline__ float zsub(float o) {
    return (o == 0.0f) ? 1.0f : o;   // reference maps exact zeros -> identity
}

// ---------------- fused kernel: build peers, grid-handshake, decode ----------
// Build phase (256 blocks x 1024 thr, 8192 warps = one half-row each, the
// proven round-9 structure): unconditional immediate-offset LDG.128 stream;
// common path per chunk = load + uint OR any-nonzero test + ONE ballot. All
// per-element masking and the 3-ballot positional compaction live in the rare
// (warp-uniform) branch; chunks whose only nonzeros lie on/below the diagonal
// enter it harmlessly with zero counts. Half-0 compacts finds ascending from
// dst[0]; half-1 walks chunks in descending column order compacting from
// dst[6] down, so rep rows (7 upper peers) end with one ascending list.
// Handshake: each block fences + bumps g_done; ONLY block 0 waits (nanosleep
// backoff), then decodes (identical to round 9) and resets g_done so every
// graph replay starts clean. Builder blocks retire freely -> no deadlock even
// across waves.
__global__ __launch_bounds__(1024, 1)
void fused_kernel(const uint4* __restrict__ w,
                  const float* __restrict__ x, float* __restrict__ out) {
    const int tid  = threadIdx.x;
    const int gw   = blockIdx.x * 32 + (tid >> 5);   // 0..8191
    const int lane = tid & 31;
    const int row  = gw >> 1;
    const int h    = gw & 1;

    // ---------------- build phase -------------------------------------------
    if (!(h == 0 && row >= 2047)) {          // half-0 entirely <= diagonal: skip
        const uint4* base = w + (size_t)row * (E / 4) + h * 512 + lane;
        int* dst = g_up + row * 7;
        int colb = h * 2048 + lane * 4;
        int total = 0;
        if (h == 0) {
#pragma unroll
            for (int i = 0; i < 16; i++) {
                uint4 v = base[i * 32];              // unconditional, imm offset
                unsigned nz = v.x | v.y | v.z | v.w;
                if (__ballot_sync(0xffffffffu, nz != 0u)) {  // warp-uniform
                    int col = colb + i * 128;
                    int c0 = (v.x != 0u) & (col     > row);
                    int c1 = (v.y != 0u) & (col + 1 > row);
                    int c2 = (v.z != 0u) & (col + 2 > row);
                    int c3 = (v.w != 0u) & (col + 3 > row);
                    int cnt = c0 + c1 + c2 + c3;
                    unsigned b0 = __ballot_sync(0xffffffffu, cnt & 1);
                    unsigned b1 = __ballot_sync(0xffffffffu, cnt & 2);
                    unsigned b2 = __ballot_sync(0xffffffffu, cnt & 4);
                    unsigned lo = (1u << lane) - 1u;
                    int idx = total + __popc(b0 & lo) + 2 * __popc(b1 & lo)
                                    + 4 * __popc(b2 & lo);
                    if (c0) dst[idx++] = col;
                    if (c1) dst[idx++] = col + 1;
                    if (c2) dst[idx++] = col + 2;
                    if (c3) dst[idx]   = col + 3;
                    total += __popc(b0) + 2 * __popc(b1) + 4 * __popc(b2);
                }
            }
            if (lane == 0) g_cntA[row] = total;
        } else {
#pragma unroll
            for (int i = 15; i >= 0; i--) {          // descending column order
                uint4 v = base[i * 32];              // unconditional, imm offset
                unsigned nz = v.x | v.y | v.z | v.w;
                if (__ballot_sync(0xffffffffu, nz != 0u)) {
                    int col = colb + i * 128;
                    int c0 = (v.x != 0u) & (col     > row);
                    int c1 = (v.y != 0u) & (col + 1 > row);
                    int c2 = (v.z != 0u) & (col + 2 > row);
                    int c3 = (v.w != 0u) & (col + 3 > row);
                    int cnt = c0 + c1 + c2 + c3;
                    unsigned b0 = __ballot_sync(0xffffffffu, cnt & 1);
                    unsigned b1 = __ballot_sync(0xffffffffu, cnt & 2);
                    unsigned b2 = __ballot_sync(0xffffffffu, cnt & 4);
                    unsigned hi = (lane == 31) ? 0u
                                               : (0xffffffffu << (lane + 1));
                    int idx = total + __popc(b0 & hi) + 2 * __popc(b1 & hi)
                                    + 4 * __popc(b2 & hi);
                    if (c3) { dst[6 - idx] = col + 3; idx++; }
                    if (c2) { dst[6 - idx] = col + 2; idx++; }
                    if (c1) { dst[6 - idx] = col + 1; idx++; }
                    if (c0) { dst[6 - idx] = col;            }
                    total += __popc(b0) + 2 * __popc(b1) + 4 * __popc(b2);
                }
            }
            if (lane == 0) g_cntB[row] = total;
        }
    }

    // ---------------- handshake ---------------------------------------------
    __threadfence();          // release: publish build stores device-wide
    __syncthreads();          // whole block's build done
    if (tid == 0) atomicAdd(&g_done, 1u);
    if (blockIdx.x != 0) return;

    if (tid == 0) {
        while (atomicAdd(&g_done, 0u) != NBLK) {     // only block 0 waits
            __nanosleep(64);                          // polite backoff
        }
        atomicExch(&g_done, 0u);                     // reset for next replay
    }
    __syncthreads();
    __threadfence();          // acquire: build stores visible before reads

    // ---------------- decode phase (block 0 only) ---------------------------
    __shared__ float sh_odd[E];      // odd messages, natural edge order
    __shared__ float sh_even[E];     // even messages, natural edge order
    __shared__ int   chk_list[NCHK]; // representative (min) edge per check
    __shared__ int   chk_ctr;

    const int t = tid;
    const float llr = x[t];

    if (t == 0) chk_ctr = 0;
    ((float4*)sh_even)[t] = make_float4(0.f, 0.f, 0.f, 0.f);
    __syncthreads();

    // claim checks: edge e is representative iff all 7 peers are above it
    int4 ca = ((const int4*)g_cntA)[t];
    int4 cb = ((const int4*)g_cntB)[t];
    if (ca.x + cb.x == 7) chk_list[atomicAdd(&chk_ctr, 1)] = 4 * t;
    if (ca.y + cb.y == 7) chk_list[atomicAdd(&chk_ctr, 1)] = 4 * t + 1;
    if (ca.z + cb.z == 7) chk_list[atomicAdd(&chk_ctr, 1)] = 4 * t + 2;
    if (ca.w + cb.w == 7) chk_list[atomicAdd(&chk_ctr, 1)] = 4 * t + 3;
    __syncthreads();

    // check owners cache their sorted 8-edge list in registers (rep = minimum)
    int id0 = 0, id1 = 0, id2 = 0, id3 = 0, id4 = 0, id5 = 0, id6 = 0, id7 = 0;
    if (t < NCHK) {
        int rep = chk_list[t];
        const int* pp = g_up + rep * 7;
        id0 = rep;
        id1 = pp[0]; id2 = pp[1]; id3 = pp[2]; id4 = pp[3];
        id5 = pp[4]; id6 = pp[5]; id7 = pp[6];
    }

    // ---- 5 BP iterations ------------------------------------------------------
#pragma unroll 1
    for (int it = 0; it < 5; it++) {
        // odd stage: vectorized, natural order (thread t = variable t)
        float4 ev = ((float4*)sh_even)[t];
        float vs = ev.x + ev.y + ev.z + ev.w;
        float4 od;
        od.x = tanh_acc(0.5f * (llr + vs - ev.x));
        od.y = tanh_acc(0.5f * (llr + vs - ev.y));
        od.z = tanh_acc(0.5f * (llr + vs - ev.z));
        od.w = tanh_acc(0.5f * (llr + vs - ev.w));
        ((float4*)sh_odd)[t] = od;
        __syncthreads();

        // even stage: 512 check owners gather 8, extrinsic products, scatter 8
        if (t < NCHK) {
            float a0 = zsub(sh_odd[id0]), a1 = zsub(sh_odd[id1]);
            float a2 = zsub(sh_odd[id2]), a3 = zsub(sh_odd[id3]);
            float a4 = zsub(sh_odd[id4]), a5 = zsub(sh_odd[id5]);
            float a6 = zsub(sh_odd[id6]), a7 = zsub(sh_odd[id7]);
            float p01 = a0 * a1, p23 = a2 * a3, p45 = a4 * a5, p67 = a6 * a7;
            float q03 = p01 * p23, q47 = p45 * p67;
            sh_even[id0] = atanh2(a1 * p23 * q47);
            sh_even[id1] = atanh2(a0 * p23 * q47);
            sh_even[id2] = atanh2(p01 * a3 * q47);
            sh_even[id3] = atanh2(p01 * a2 * q47);
            sh_even[id4] = atanh2(q03 * a5 * p67);
            sh_even[id5] = atanh2(q03 * a4 * p67);
            sh_even[id6] = atanh2(q03 * p45 * a7);
            sh_even[id7] = atanh2(q03 * p45 * a6);
        }
        __syncthreads();
    }

    // ---- epilogue: out[n] = sigmoid(x[n] + sum of even over var n) ------------
    float4 ev = ((float4*)sh_even)[t];
    float z = llr + ev.x + ev.y + ev.z + ev.w;
    out[t] = __fdividef(1.0f, 1.0f + __expf(-z));
}

// ---------------- launch ------------------------------------------------------
extern "C" void kernel_launch(void* const* d_in, const int* in_sizes, int n_in,
                              void* d_out, int out_size) {
    (void)in_sizes; (void)n_in; (void)out_size;
    const float* x = (const float*)d_in[0];
    const uint4* w = (const uint4*)d_in[2];   // w_odd_to_even [E,E]
    float* out = (float*)d_out;

    fused_kernel<<<NBLK, 1024>>>(w, x, out);  // single launch: build + decode
}

// round 13
// speedup vs baseline: 1.0300x; 1.0300x over previous
#include <cuda_runtime.h>

#define E    4096
#define NVAR 1024
#define NCHK 512
#define NBLK 128
#define EPS32   1.1920929e-07f
#define LN2F    0.6931471805599453f

// Upper-triangle peers of each edge (columns > row), ascending. Rows with
// cntA+cntB==7 (check representatives) have complete sorted lists; only those
// are ever read by decode. g_cntA for rows >= 2047 is never written: it stays
// 0 from BSS zero-init (those rows have no upper peers in cols [0,2048) by
// construction, so 0 is the correct count on every replay).
__device__ int g_up[E * 7];
__device__ __align__(16) int g_cntA[E];   // peers found in cols [0,2048)
__device__ __align__(16) int g_cntB[E];   // peers found in cols [2048,4096)
__device__ unsigned g_done = 0;           // grid handshake (reset every run)

// ---------------- math helpers -----------------------------------------------
__device__ __forceinline__ float tanh_acc(float a) {
    // tanh(a) = 1 - 2/(exp(2a)+1); inf-safe (saturates to +-1 exactly)
    return 1.0f - __fdividef(2.0f, __expf(2.0f * a) + 1.0f);
}

__device__ __forceinline__ float atanh2(float v) {
    // reference clamps: v>=1 -> 1-eps, v<=-1 -> -1+eps (exact copy)
    v = (v >= 1.0f) ? (1.0f - EPS32) : v;
    v = (v <= -1.0f) ? (-1.0f + EPS32) : v;
    // 2*atanh(v) = ln2*(lg2(1+v) - lg2(1-v)); two independent MUFU lg2
    return LN2F * (__log2f(1.0f + v) - __log2f(1.0f - v));
}

__device__ __forceinline__ float zsub(float o) {
    return (o == 0.0f) ? 1.0f : o;   // reference maps exact zeros -> identity
}

// ---------------- fused kernel: build peers, grid-handshake, decode ----------
// SINGLE WAVE: 128 blocks x 1024 threads (128 < 148 SMs), so every builder
// block is resident from t=0 and block 0 never waits on a second wave (the
// round-12 regression). Warp gw owns row gw as two fixed 16-chunk passes with
// every LDG.128 unconditional at an immediate offset (the proven round-3 load
// discipline). Pass h=0 (cols [0,2048)) compacts finds ascending from dst[0],
// skipped outright for rows >= 2047; pass h=1 (cols [2048,4096)) walks chunks
// in descending column order compacting from dst[6] down, so rep rows (7
// upper peers) end with one ascending list. Common path per chunk = load +
// uint OR + ONE ballot; masking and the 3-ballot compaction are in the rare
// warp-uniform branch (below-diagonal chunks enter harmlessly with 0 counts).
// Handshake: each block fences + bumps g_done; ONLY block 0 waits (nanosleep
// backoff), resets g_done for replay determinism, then decodes.
__global__ __launch_bounds__(1024, 1)
void fused_kernel(const uint4* __restrict__ w,
                  const float* __restrict__ x, float* __restrict__ out) {
    const int tid  = threadIdx.x;
    const int row  = blockIdx.x * 32 + (tid >> 5);   // 0..4095: one row/warp
    const int lane = tid & 31;

    // ---------------- build phase -------------------------------------------
    const uint4* rbase = w + (size_t)row * (E / 4) + lane;
    int* dst = g_up + row * 7;

    if (row < 2047) {                        // pass h=0: cols [0,2048)
        int total = 0;
#pragma unroll
        for (int i = 0; i < 16; i++) {
            uint4 v = rbase[i * 32];                 // unconditional, imm offset
            unsigned nz = v.x | v.y | v.z | v.w;
            if (__ballot_sync(0xffffffffu, nz != 0u)) {      // warp-uniform
                int col = i * 128 + lane * 4;
                int c0 = (v.x != 0u) & (col     > row);
                int c1 = (v.y != 0u) & (col + 1 > row);
                int c2 = (v.z != 0u) & (col + 2 > row);
                int c3 = (v.w != 0u) & (col + 3 > row);
                int cnt = c0 + c1 + c2 + c3;
                unsigned b0 = __ballot_sync(0xffffffffu, cnt & 1);
                unsigned b1 = __ballot_sync(0xffffffffu, cnt & 2);
                unsigned b2 = __ballot_sync(0xffffffffu, cnt & 4);
                unsigned lo = (1u << lane) - 1u;
                int idx = total + __popc(b0 & lo) + 2 * __popc(b1 & lo)
                                + 4 * __popc(b2 & lo);
                if (c0) dst[idx++] = col;
                if (c1) dst[idx++] = col + 1;
                if (c2) dst[idx++] = col + 2;
                if (c3) dst[idx]   = col + 3;
                total += __popc(b0) + 2 * __popc(b1) + 4 * __popc(b2);
            }
        }
        if (lane == 0) g_cntA[row] = total;
    }

    {                                        // pass h=1: cols [2048,4096)
        const uint4* hbase = rbase + 512;
        int total = 0;
#pragma unroll
        for (int i = 15; i >= 0; i--) {              // descending column order
            uint4 v = hbase[i * 32];                 // unconditional, imm offset
            unsigned nz = v.x | v.y | v.z | v.w;
            if (__ballot_sync(0xffffffffu, nz != 0u)) {
                int col = 2048 + i * 128 + lane * 4;
                int c0 = (v.x != 0u) & (col     > row);
                int c1 = (v.y != 0u) & (col + 1 > row);
                int c2 = (v.z != 0u) & (col + 2 > row);
                int c3 = (v.w != 0u) & (col + 3 > row);
                int cnt = c0 + c1 + c2 + c3;
                unsigned b0 = __ballot_sync(0xffffffffu, cnt & 1);
                unsigned b1 = __ballot_sync(0xffffffffu, cnt & 2);
                unsigned b2 = __ballot_sync(0xffffffffu, cnt & 4);
                unsigned hi = (lane == 31) ? 0u : (0xffffffffu << (lane + 1));
                int idx = total + __popc(b0 & hi) + 2 * __popc(b1 & hi)
                                + 4 * __popc(b2 & hi);
                if (c3) { dst[6 - idx] = col + 3; idx++; }
                if (c2) { dst[6 - idx] = col + 2; idx++; }
                if (c1) { dst[6 - idx] = col + 1; idx++; }
                if (c0) { dst[6 - idx] = col;            }
                total += __popc(b0) + 2 * __popc(b1) + 4 * __popc(b2);
            }
        }
        if (lane == 0) g_cntB[row] = total;
    }

    // ---------------- handshake ---------------------------------------------
    __threadfence();          // release: publish build stores device-wide
    __syncthreads();          // whole block's build done
    if (tid == 0) atomicAdd(&g_done, 1u);
    if (blockIdx.x != 0) return;

    if (tid == 0) {
        while (atomicAdd(&g_done, 0u) != NBLK) {     // only block 0 waits
            __nanosleep(64);                          // polite backoff
        }
        atomicExch(&g_done, 0u);                     // reset for next replay
    }
    __syncthreads();
    __threadfence();          // acquire: build stores visible before reads

    // ---------------- decode phase (block 0 only) ---------------------------
    __shared__ float sh_odd[E];      // odd messages, natural edge order
    __shared__ float sh_even[E];     // even messages, natural edge order
    __shared__ int   chk_list[NCHK]; // representative (min) edge per check
    __shared__ int   chk_ctr;

    const int t = tid;
    const float llr = x[t];

    if (t == 0) chk_ctr = 0;
    ((float4*)sh_even)[t] = make_float4(0.f, 0.f, 0.f, 0.f);
    __syncthreads();

    // claim checks: edge e is representative iff all 7 peers are above it
    int4 ca = ((const int4*)g_cntA)[t];
    int4 cb = ((const int4*)g_cntB)[t];
    if (ca.x + cb.x == 7) chk_list[atomicAdd(&chk_ctr, 1)] = 4 * t;
    if (ca.y + cb.y == 7) chk_list[atomicAdd(&chk_ctr, 1)] = 4 * t + 1;
    if (ca.z + cb.z == 7) chk_list[atomicAdd(&chk_ctr, 1)] = 4 * t + 2;
    if (ca.w + cb.w == 7) chk_list[atomicAdd(&chk_ctr, 1)] = 4 * t + 3;
    __syncthreads();

    // check owners cache their sorted 8-edge list in registers (rep = minimum)
    int id0 = 0, id1 = 0, id2 = 0, id3 = 0, id4 = 0, id5 = 0, id6 = 0, id7 = 0;
    if (t < NCHK) {
        int rep = chk_list[t];
        const int* pp = g_up + rep * 7;
        id0 = rep;
        id1 = pp[0]; id2 = pp[1]; id3 = pp[2]; id4 = pp[3];
        id5 = pp[4]; id6 = pp[5]; id7 = pp[6];
    }

    // ---- 5 BP iterations ------------------------------------------------------
#pragma unroll 1
    for (int it = 0; it < 5; it++) {
        // odd stage: vectorized, natural order (thread t = variable t)
        float4 ev = ((float4*)sh_even)[t];
        float vs = ev.x + ev.y + ev.z + ev.w;
        float4 od;
        od.x = tanh_acc(0.5f * (llr + vs - ev.x));
        od.y = tanh_acc(0.5f * (llr + vs - ev.y));
        od.z = tanh_acc(0.5f * (llr + vs - ev.z));
        od.w = tanh_acc(0.5f * (llr + vs - ev.w));
        ((float4*)sh_odd)[t] = od;
        __syncthreads();

        // even stage: 512 check owners gather 8, extrinsic products, scatter 8
        if (t < NCHK) {
            float a0 = zsub(sh_odd[id0]), a1 = zsub(sh_odd[id1]);
            float a2 = zsub(sh_odd[id2]), a3 = zsub(sh_odd[id3]);
            float a4 = zsub(sh_odd[id4]), a5 = zsub(sh_odd[id5]);
            float a6 = zsub(sh_odd[id6]), a7 = zsub(sh_odd[id7]);
            float p01 = a0 * a1, p23 = a2 * a3, p45 = a4 * a5, p67 = a6 * a7;
            float q03 = p01 * p23, q47 = p45 * p67;
            sh_even[id0] = atanh2(a1 * p23 * q47);
            sh_even[id1] = atanh2(a0 * p23 * q47);
            sh_even[id2] = atanh2(p01 * a3 * q47);
            sh_even[id3] = atanh2(p01 * a2 * q47);
            sh_even[id4] = atanh2(q03 * a5 * p67);
            sh_even[id5] = atanh2(q03 * a4 * p67);
            sh_even[id6] = atanh2(q03 * p45 * a7);
            sh_even[id7] = atanh2(q03 * p45 * a6);
        }
        __syncthreads();
    }

    // ---- epilogue: out[n] = sigmoid(x[n] + sum of even over var n) ------------
    float4 ev = ((float4*)sh_even)[t];
    float z = llr + ev.x + ev.y + ev.z + ev.w;
    out[t] = __fdividef(1.0f, 1.0f + __expf(-z));
}

// ---------------- launch ------------------------------------------------------
extern "C" void kernel_launch(void* const* d_in, const int* in_sizes, int n_in,
                              void* d_out, int out_size) {
    (void)in_sizes; (void)n_in; (void)out_size;
    const float* x = (const float*)d_in[0];
    const uint4* w = (const uint4*)d_in[2];   // w_odd_to_even [E,E]
    float* out = (float*)d_out;

    fused_kernel<<<NBLK, 1024>>>(w, x, out);  // one launch, one wave
}

// round 16
// speedup vs baseline: 1.1433x; 1.1100x over previous
#include <cuda_runtime.h>

#define E    4096
#define NVAR 1024
#define NCHK 512
#define EPS32   1.1920929e-07f
#define LN2F    0.6931471805599453f

// Upper-triangle peers of each edge (columns > row), ascending. Rows with
// cntA+cntB==7 (check representatives) have complete sorted lists; only those
// are ever read by decode. g_cntA for rows >= 2047 is never written: it stays
// 0 from zero-init, which is the correct count (those rows have no upper
// peers in cols [0,2048)).
__device__ int g_up[E * 7];
__device__ __align__(16) int g_cntA[E];   // upper peers found in cols [0,2048)
__device__ __align__(16) int g_cntB[E];   // upper peers found in cols [2048,4096)

// ---------------- kernel A: half-row upper-triangle scan ---------------------
// Round-9 grid and load types verbatim (8192 warps, one half-row each,
// 256-thread blocks, float4 loads, float != 0 compares); the ONLY delta vs
// the round-9 source that passed at 18.9us is the gate: common path per chunk
// is load + 4 FSETP + OR + ONE ballot, with the 3-ballot positional
// compaction moved inside the rare warp-uniform branch. Chunks whose nonzeros
// all lie on/below the diagonal enter the branch harmlessly (cnt=0 lanes).
// Half-0 (cols [0,2048)) is skipped outright for rows >= 2047 and compacts
// finds ascending from dst[0]; half-1 walks its chunks in descending column
// order compacting from dst[6] down, so rep rows (exactly 7 upper peers) end
// with one complete ascending list.
__global__ void build_peers_kernel(const float4* __restrict__ w) {
    const int gw   = (blockIdx.x * blockDim.x + threadIdx.x) >> 5;  // 0..8191
    const int lane = threadIdx.x & 31;
    const int row  = gw >> 1;
    const int h    = gw & 1;
    if (h == 0 && row >= 2047) return;       // half-0 entirely <= diagonal
    const float4* base = w + (size_t)row * (E / 4) + h * 512 + lane;
    int* dst = g_up + row * 7;
    const int colb = h * 2048 + lane * 4;
    int total = 0;
    if (h == 0) {
#pragma unroll
        for (int i = 0; i < 16; i++) {
            float4 v = base[i * 32];                 // unconditional, imm offset
            int c0 = (v.x != 0.0f) & (colb + i * 128     > row);
            int c1 = (v.y != 0.0f) & (colb + i * 128 + 1 > row);
            int c2 = (v.z != 0.0f) & (colb + i * 128 + 2 > row);
            int c3 = (v.w != 0.0f) & (colb + i * 128 + 3 > row);
            int cnt = c0 + c1 + c2 + c3;
            if (__ballot_sync(0xffffffffu, cnt != 0)) {      // warp-uniform
                int col = colb + i * 128;
                unsigned b0 = __ballot_sync(0xffffffffu, cnt & 1);
                unsigned b1 = __ballot_sync(0xffffffffu, cnt & 2);
                unsigned b2 = __ballot_sync(0xffffffffu, cnt & 4);
                unsigned lo = (1u << lane) - 1u;
                int idx = total + __popc(b0 & lo) + 2 * __popc(b1 & lo)
                                + 4 * __popc(b2 & lo);
                if (c0) dst[idx++] = col;
                if (c1) dst[idx++] = col + 1;
                if (c2) dst[idx++] = col + 2;
                if (c3) dst[idx]   = col + 3;
                total += __popc(b0) + 2 * __popc(b1) + 4 * __popc(b2);
            }
        }
        if (lane == 0) g_cntA[row] = total;
    } else {
#pragma unroll
        for (int i = 15; i >= 0; i--) {              // descending column order
            float4 v = base[i * 32];                 // unconditional, imm offset
            int c0 = (v.x != 0.0f) & (colb + i * 128     > row);
            int c1 = (v.y != 0.0f) & (colb + i * 128 + 1 > row);
            int c2 = (v.z != 0.0f) & (colb + i * 128 + 2 > row);
            int c3 = (v.w != 0.0f) & (colb + i * 128 + 3 > row);
            int cnt = c0 + c1 + c2 + c3;
            if (__ballot_sync(0xffffffffu, cnt != 0)) {
                int col = colb + i * 128;
                unsigned b0 = __ballot_sync(0xffffffffu, cnt & 1);
                unsigned b1 = __ballot_sync(0xffffffffu, cnt & 2);
                unsigned b2 = __ballot_sync(0xffffffffu, cnt & 4);
                unsigned hi = (lane == 31) ? 0u : (0xffffffffu << (lane + 1));
                int idx = total + __popc(b0 & hi) + 2 * __popc(b1 & hi)
                                + 4 * __popc(b2 & hi);
                if (c3) { dst[6 - idx] = col + 3; idx++; }
                if (c2) { dst[6 - idx] = col + 2; idx++; }
                if (c1) { dst[6 - idx] = col + 1; idx++; }
                if (c0) { dst[6 - idx] = col;            }
                total += __popc(b0) + 2 * __popc(b1) + 4 * __popc(b2);
            }
        }
        if (lane == 0) g_cntB[row] = total;
    }
}

// ---------------- math helpers -----------------------------------------------
__device__ __forceinline__ float tanh_acc(float a) {
    // tanh(a) = 1 - 2/(exp(2a)+1); inf-safe (saturates to +-1 exactly)
    return 1.0f - __fdividef(2.0f, __expf(2.0f * a) + 1.0f);
}

__device__ __forceinline__ float atanh2(float v) {
    // reference clamps: v>=1 -> 1-eps, v<=-1 -> -1+eps (exact copy)
    v = (v >= 1.0f) ? (1.0f - EPS32) : v;
    v = (v <= -1.0f) ? (-1.0f + EPS32) : v;
    // 2*atanh(v) = ln2*(lg2(1+v) - lg2(1-v)); two independent MUFU lg2
    return LN2F * (__log2f(1.0f + v) - __log2f(1.0f - v));
}

__device__ __forceinline__ float zsub(float o) {
    return (o == 0.0f) ? 1.0f : o;   // reference maps exact zeros -> identity
}

// ---------------- kernel B: full decode, one persistent block ----------------
// (Round-9 decode verbatim: measured stable at ~10.4us.)
__global__ __launch_bounds__(1024, 1)
void decode_kernel(const float* __restrict__ x, float* __restrict__ out) {
    __shared__ float sh_odd[E];      // odd messages, natural edge order
    __shared__ float sh_even[E];     // even messages, natural edge order
    __shared__ int   chk_list[NCHK]; // representative (min) edge per check
    __shared__ int   chk_ctr;

    const int t = threadIdx.x;
    const float llr = x[t];

    if (t == 0) chk_ctr = 0;
    ((float4*)sh_even)[t] = make_float4(0.f, 0.f, 0.f, 0.f);
    __syncthreads();

    // claim checks: edge e is representative iff all 7 peers are above it
    int4 ca = ((const int4*)g_cntA)[t];
    int4 cb = ((const int4*)g_cntB)[t];
    if (ca.x + cb.x == 7) chk_list[atomicAdd(&chk_ctr, 1)] = 4 * t;
    if (ca.y + cb.y == 7) chk_list[atomicAdd(&chk_ctr, 1)] = 4 * t + 1;
    if (ca.z + cb.z == 7) chk_list[atomicAdd(&chk_ctr, 1)] = 4 * t + 2;
    if (ca.w + cb.w == 7) chk_list[atomicAdd(&chk_ctr, 1)] = 4 * t + 3;
    __syncthreads();

    // check owners cache their sorted 8-edge list in registers (rep = minimum)
    int id0 = 0, id1 = 0, id2 = 0, id3 = 0, id4 = 0, id5 = 0, id6 = 0, id7 = 0;
    if (t < NCHK) {
        int rep = chk_list[t];
        const int* pp = g_up + rep * 7;
        id0 = rep;
        id1 = pp[0]; id2 = pp[1]; id3 = pp[2]; id4 = pp[3];
        id5 = pp[4]; id6 = pp[5]; id7 = pp[6];
    }

    // ---- 5 BP iterations ------------------------------------------------------
#pragma unroll 1
    for (int it = 0; it < 5; it++) {
        // odd stage: vectorized, natural order (thread t = variable t)
        float4 ev = ((float4*)sh_even)[t];
        float vs = ev.x + ev.y + ev.z + ev.w;
        float4 od;
        od.x = tanh_acc(0.5f * (llr + vs - ev.x));
        od.y = tanh_acc(0.5f * (llr + vs - ev.y));
        od.z = tanh_acc(0.5f * (llr + vs - ev.z));
        od.w = tanh_acc(0.5f * (llr + vs - ev.w));
        ((float4*)sh_odd)[t] = od;
        __syncthreads();

        // even stage: 512 check owners gather 8, extrinsic products, scatter 8
        if (t < NCHK) {
            float a0 = zsub(sh_odd[id0]), a1 = zsub(sh_odd[id1]);
            float a2 = zsub(sh_odd[id2]), a3 = zsub(sh_odd[id3]);
            float a4 = zsub(sh_odd[id4]), a5 = zsub(sh_odd[id5]);
            float a6 = zsub(sh_odd[id6]), a7 = zsub(sh_odd[id7]);
            float p01 = a0 * a1, p23 = a2 * a3, p45 = a4 * a5, p67 = a6 * a7;
            float q03 = p01 * p23, q47 = p45 * p67;
            sh_even[id0] = atanh2(a1 * p23 * q47);
            sh_even[id1] = atanh2(a0 * p23 * q47);
            sh_even[id2] = atanh2(p01 * a3 * q47);
            sh_even[id3] = atanh2(p01 * a2 * q47);
            sh_even[id4] = atanh2(q03 * a5 * p67);
            sh_even[id5] = atanh2(q03 * a4 * p67);
            sh_even[id6] = atanh2(q03 * p45 * a7);
            sh_even[id7] = atanh2(q03 * p45 * a6);
        }
        __syncthreads();
    }

    // ---- epilogue: out[n] = sigmoid(x[n] + sum of even over var n) ------------
    float4 ev = ((float4*)sh_even)[t];
    float z = llr + ev.x + ev.y + ev.z + ev.w;
    out[t] = __fdividef(1.0f, 1.0f + __expf(-z));
}

// ---------------- launch ------------------------------------------------------
extern "C" void kernel_launch(void* const* d_in, const int* in_sizes, int n_in,
                              void* d_out, int out_size) {
    (void)in_sizes; (void)n_in; (void)out_size;
    const float*  x = (const float*)d_in[0];
    const float4* w = (const float4*)d_in[2];   // w_odd_to_even [E,E]
    float* out = (float*)d_out;

    build_peers_kernel<<<1024, 256>>>(w);   // 8192 half-row warps, slim gate
    decode_kernel<<<1, 1024>>>(x, out);
}